// round 9
// baseline (speedup 1.0000x reference)
#include <cuda_runtime.h>
#include <cuda_bf16.h>
#include <math.h>

// Problem constants
#define B     32
#define CIN   512
#define HW    4096          // 64*64
#define MID   32            // 512/16
#define COUT  512

#define TILE_STRIDE 33                         // padded transpose row stride
#define W1_FLOATS   (MID * CIN)                // 16384
#define TILE_FLOATS (16 * 32 * TILE_STRIDE)    // 16896
#define FC_DYN_SMEM ((W1_FLOATS + TILE_FLOATS) * 4)   // ~130 KB

// Scratch (no cudaMalloc allowed)
__device__ float g_pooled[B * CIN];   // [B, CIN] means

// ---------------------------------------------------------------------------
// Kernel 1: global average pool.  (UNCHANGED — measured 6.9 TB/s, ~86% HBM)
// ---------------------------------------------------------------------------
__global__ __launch_bounds__(256) void se_pool_kernel(const float* __restrict__ x) {
    const int row = blockIdx.x;                 // 0 .. B*CIN-1
    const float4* __restrict__ p =
        reinterpret_cast<const float4*>(x + (size_t)row * HW);
    const int tid = threadIdx.x;

    float4 v0 = p[tid];
    float4 v1 = p[tid + 256];
    float4 v2 = p[tid + 512];
    float4 v3 = p[tid + 768];

    float s = (v0.x + v0.y) + (v0.z + v0.w)
            + (v1.x + v1.y) + (v1.z + v1.w)
            + (v2.x + v2.y) + (v2.z + v2.w)
            + (v3.x + v3.y) + (v3.z + v3.w);

    #pragma unroll
    for (int off = 16; off > 0; off >>= 1)
        s += __shfl_xor_sync(0xFFFFFFFFu, s, off);

    __shared__ float warp_sums[8];
    const int lane = tid & 31;
    const int wid  = tid >> 5;
    if (lane == 0) warp_sums[wid] = s;
    __syncthreads();

    if (wid == 0) {
        float t = (lane < 8) ? warp_sums[lane] : 0.0f;
        #pragma unroll
        for (int off = 4; off > 0; off >>= 1)
            t += __shfl_xor_sync(0xFFFFFFFFu, t, off);
        if (lane == 0)
            g_pooled[row] = t * (1.0f / (float)HW);
    }
}

// ---------------------------------------------------------------------------
// Kernel 2: FC chain, launched with PDL (programmatic stream serialization).
// PRE-SYNC (overlapped with pool kernel): prefetch all weights into smem.
//   - s_w1: w1 verbatim [MID][CIN], coalesced float4 loads.
//   - s_tile: per-warp transposed 32x32 w2 tiles (pad 33, conflict-free).
// cudaGridDependencySynchronize() -> pool results visible.
// POST-SYNC (exposed tail, ~1.5k cycles):
//   phase 1: warp w computes mids {2w,2w+1} from smem (dot + butterfly).
//   phase 2: output o = 32*wid+lane via 32 independent smem FMAs + sigmoid.
// ---------------------------------------------------------------------------
__global__ __launch_bounds__(512) void se_fc_kernel(
    const float* __restrict__ w1, const float* __restrict__ b1,
    const float* __restrict__ w2, const float* __restrict__ b2,
    float* __restrict__ out)
{
    extern __shared__ float dyn[];
    float* __restrict__ s_w1   = dyn;               // [MID * CIN]
    float* __restrict__ s_tile = dyn + W1_FLOATS;   // [16][32 * TILE_STRIDE]

    __shared__ float s_pooled[CIN];
    __shared__ float s_h[MID];

    const int b    = blockIdx.x;
    const int tid  = threadIdx.x;
    const int lane = tid & 31;
    const int wid  = tid >> 5;

    // ---- PRE-SYNC preamble: weight prefetch (independent of pool output) ----
    {
        // w1: 16384 floats = 4096 float4; 512 threads x 8 each, coalesced
        const float4* __restrict__ w1v = reinterpret_cast<const float4*>(w1);
        float4* __restrict__ s_w1v = reinterpret_cast<float4*>(s_w1);
        #pragma unroll
        for (int i = 0; i < 8; i++)
            s_w1v[tid + 512 * i] = w1v[tid + 512 * i];

        // w2: warp wid transposes its rows [32*wid, 32*wid+32) into its tile
        float* __restrict__ tile = s_tile + wid * (32 * TILE_STRIDE);
        const int base = wid * 32;
        #pragma unroll
        for (int i = 0; i < 32; i++)            // coalesced LDG, conflict-free STS
            tile[i * TILE_STRIDE + lane] = w2[(size_t)(base + i) * MID + lane];
    }

    // ---- Wait for pool kernel completion + memory visibility ----
    cudaGridDependencySynchronize();
    __syncthreads();

    s_pooled[tid] = g_pooled[b * CIN + tid];
    __syncthreads();

    // Phase 1: warp wid computes mids {2*wid, 2*wid+1} from smem
    {
        const int m0 = wid * 2;
        const float* __restrict__ w1r0 = s_w1 + (m0 + 0) * CIN;
        const float* __restrict__ w1r1 = s_w1 + (m0 + 1) * CIN;

        float a0 = 0.f, a1 = 0.f;
        #pragma unroll
        for (int j = 0; j < 16; j++) {
            const int k = lane + 32 * j;
            const float pv = s_pooled[k];
            a0 = fmaf(pv, w1r0[k], a0);
            a1 = fmaf(pv, w1r1[k], a1);
        }
        #pragma unroll
        for (int off = 16; off > 0; off >>= 1) {
            a0 += __shfl_xor_sync(0xFFFFFFFFu, a0, off);
            a1 += __shfl_xor_sync(0xFFFFFFFFu, a1, off);
        }
        if (lane == 0) {
            float h0 = a0 + b1[m0 + 0];
            float h1 = a1 + b1[m0 + 1];
            s_h[m0 + 0] = h0 > 0.f ? h0 : 0.f;
            s_h[m0 + 1] = h1 > 0.f ? h1 : 0.f;
        }
    }
    __syncthreads();

    // Phase 2: output o = 32*wid + lane; 32 independent FMAs from smem.
    {
        const float* __restrict__ tile = s_tile + wid * (32 * TILE_STRIDE);
        const int o = wid * 32 + lane;

        float acc = b2[o];
        #pragma unroll
        for (int m = 0; m < MID; m++)           // tile row conflict-free (pad 33)
            acc = fmaf(tile[lane * TILE_STRIDE + m], s_h[m], acc);

        out[(size_t)b * COUT + o] = 1.0f / (1.0f + __expf(-acc));
    }
}

// ---------------------------------------------------------------------------
extern "C" void kernel_launch(void* const* d_in, const int* in_sizes, int n_in,
                              void* d_out, int out_size) {
    const float* x  = (const float*)d_in[0];
    const float* w1 = (const float*)d_in[1];
    const float* b1 = (const float*)d_in[2];
    const float* w2 = (const float*)d_in[3];
    const float* b2 = (const float*)d_in[4];
    float* out = (float*)d_out;

    se_pool_kernel<<<B * CIN, 256>>>(x);

    cudaFuncSetAttribute(se_fc_kernel,
                         cudaFuncAttributeMaxDynamicSharedMemorySize, FC_DYN_SMEM);

    cudaLaunchConfig_t cfg = {};
    cfg.gridDim          = dim3(B, 1, 1);
    cfg.blockDim         = dim3(512, 1, 1);
    cfg.dynamicSmemBytes = FC_DYN_SMEM;
    cfg.stream           = 0;

    cudaLaunchAttribute attrs[1];
    attrs[0].id = cudaLaunchAttributeProgrammaticStreamSerialization;
    attrs[0].val.programmaticStreamSerializationAllowed = 1;
    cfg.attrs    = attrs;
    cfg.numAttrs = 1;

    cudaLaunchKernelEx(&cfg, se_fc_kernel, w1, b1, w2, b2, out);
}

// round 10
// speedup vs baseline: 1.0091x; 1.0091x over previous
#include <cuda_runtime.h>
#include <cuda_bf16.h>
#include <math.h>

// Problem constants
#define B     32
#define CIN   512
#define HW    4096          // 64*64
#define MID   32            // 512/16
#define COUT  512

#define TILE_STRIDE 33                         // padded transpose row stride
#define W1_FLOATS   (MID * CIN)                // 16384
#define TILE_FLOATS (16 * 32 * TILE_STRIDE)    // 16896
#define FC_DYN_SMEM ((W1_FLOATS + TILE_FLOATS) * 4)   // ~130 KB

// Scratch (no cudaMalloc allowed)
__device__ float g_pooled[B * CIN];   // [B, CIN] means

// ---------------------------------------------------------------------------
// Kernel 1: global average pool.  (identical math — measured 6.9 TB/s)
// NEW: explicit PDL trigger at CTA start so the fc kernel launches while the
// pool's last wave is still running (trigger fires when ALL CTAs executed it).
// ---------------------------------------------------------------------------
__global__ __launch_bounds__(256) void se_pool_kernel(const float* __restrict__ x) {
    cudaTriggerProgrammaticLaunchCompletion();

    const int row = blockIdx.x;                 // 0 .. B*CIN-1
    const float4* __restrict__ p =
        reinterpret_cast<const float4*>(x + (size_t)row * HW);
    const int tid = threadIdx.x;

    float4 v0 = p[tid];
    float4 v1 = p[tid + 256];
    float4 v2 = p[tid + 512];
    float4 v3 = p[tid + 768];

    float s = (v0.x + v0.y) + (v0.z + v0.w)
            + (v1.x + v1.y) + (v1.z + v1.w)
            + (v2.x + v2.y) + (v2.z + v2.w)
            + (v3.x + v3.y) + (v3.z + v3.w);

    #pragma unroll
    for (int off = 16; off > 0; off >>= 1)
        s += __shfl_xor_sync(0xFFFFFFFFu, s, off);

    __shared__ float warp_sums[8];
    const int lane = tid & 31;
    const int wid  = tid >> 5;
    if (lane == 0) warp_sums[wid] = s;
    __syncthreads();

    if (wid == 0) {
        float t = (lane < 8) ? warp_sums[lane] : 0.0f;
        #pragma unroll
        for (int off = 4; off > 0; off >>= 1)
            t += __shfl_xor_sync(0xFFFFFFFFu, t, off);
        if (lane == 0)
            g_pooled[row] = t * (1.0f / (float)HW);
    }
}

// ---------------------------------------------------------------------------
// Kernel 2: FC chain, launched with PDL.
// PRE-SYNC (overlapped with pool's last wave): prefetch all weights to smem.
// cudaGridDependencySynchronize() -> pool grid complete + memory visible.
// POST-SYNC (short exposed tail): pooled load -> phase1 dot+reduce -> phase2
// smem FMAs -> sigmoid -> store.
// ---------------------------------------------------------------------------
__global__ __launch_bounds__(512) void se_fc_kernel(
    const float* __restrict__ w1, const float* __restrict__ b1,
    const float* __restrict__ w2, const float* __restrict__ b2,
    float* __restrict__ out)
{
    extern __shared__ float dyn[];
    float* __restrict__ s_w1   = dyn;               // [MID * CIN]
    float* __restrict__ s_tile = dyn + W1_FLOATS;   // [16][32 * TILE_STRIDE]

    __shared__ float s_pooled[CIN];
    __shared__ float s_h[MID];

    const int b    = blockIdx.x;
    const int tid  = threadIdx.x;
    const int lane = tid & 31;
    const int wid  = tid >> 5;

    // ---- PRE-SYNC preamble: weight prefetch (independent of pool output) ----
    {
        const float4* __restrict__ w1v = reinterpret_cast<const float4*>(w1);
        float4* __restrict__ s_w1v = reinterpret_cast<float4*>(s_w1);
        #pragma unroll
        for (int i = 0; i < 8; i++)
            s_w1v[tid + 512 * i] = w1v[tid + 512 * i];

        float* __restrict__ tile = s_tile + wid * (32 * TILE_STRIDE);
        const int base = wid * 32;
        #pragma unroll
        for (int i = 0; i < 32; i++)            // coalesced LDG, conflict-free STS
            tile[i * TILE_STRIDE + lane] = w2[(size_t)(base + i) * MID + lane];
    }

    // ---- Wait for pool kernel completion + memory visibility ----
    cudaGridDependencySynchronize();
    __syncthreads();

    s_pooled[tid] = g_pooled[b * CIN + tid];
    __syncthreads();

    // Phase 1: warp wid computes mids {2*wid, 2*wid+1} from smem
    {
        const int m0 = wid * 2;
        const float* __restrict__ w1r0 = s_w1 + (m0 + 0) * CIN;
        const float* __restrict__ w1r1 = s_w1 + (m0 + 1) * CIN;

        float a0 = 0.f, a1 = 0.f;
        #pragma unroll
        for (int j = 0; j < 16; j++) {
            const int k = lane + 32 * j;
            const float pv = s_pooled[k];
            a0 = fmaf(pv, w1r0[k], a0);
            a1 = fmaf(pv, w1r1[k], a1);
        }
        #pragma unroll
        for (int off = 16; off > 0; off >>= 1) {
            a0 += __shfl_xor_sync(0xFFFFFFFFu, a0, off);
            a1 += __shfl_xor_sync(0xFFFFFFFFu, a1, off);
        }
        if (lane == 0) {
            float h0 = a0 + b1[m0 + 0];
            float h1 = a1 + b1[m0 + 1];
            s_h[m0 + 0] = h0 > 0.f ? h0 : 0.f;
            s_h[m0 + 1] = h1 > 0.f ? h1 : 0.f;
        }
    }
    __syncthreads();

    // Phase 2: output o = 32*wid + lane; 32 independent FMAs from smem.
    {
        const float* __restrict__ tile = s_tile + wid * (32 * TILE_STRIDE);
        const int o = wid * 32 + lane;

        float acc = b2[o];
        #pragma unroll
        for (int m = 0; m < MID; m++)           // tile row conflict-free (pad 33)
            acc = fmaf(tile[lane * TILE_STRIDE + m], s_h[m], acc);

        out[(size_t)b * COUT + o] = 1.0f / (1.0f + __expf(-acc));
    }
}

// ---------------------------------------------------------------------------
extern "C" void kernel_launch(void* const* d_in, const int* in_sizes, int n_in,
                              void* d_out, int out_size) {
    const float* x  = (const float*)d_in[0];
    const float* w1 = (const float*)d_in[1];
    const float* b1 = (const float*)d_in[2];
    const float* w2 = (const float*)d_in[3];
    const float* b2 = (const float*)d_in[4];
    float* out = (float*)d_out;

    se_pool_kernel<<<B * CIN, 256>>>(x);

    cudaFuncSetAttribute(se_fc_kernel,
                         cudaFuncAttributeMaxDynamicSharedMemorySize, FC_DYN_SMEM);

    cudaLaunchConfig_t cfg = {};
    cfg.gridDim          = dim3(B, 1, 1);
    cfg.blockDim         = dim3(512, 1, 1);
    cfg.dynamicSmemBytes = FC_DYN_SMEM;
    cfg.stream           = 0;

    cudaLaunchAttribute attrs[1];
    attrs[0].id = cudaLaunchAttributeProgrammaticStreamSerialization;
    attrs[0].val.programmaticStreamSerializationAllowed = 1;
    cfg.attrs    = attrs;
    cfg.numAttrs = 1;

    cudaLaunchKernelEx(&cfg, se_fc_kernel, w1, b1, w2, b2, out);
}